// round 6
// baseline (speedup 1.0000x reference)
#include <cuda_runtime.h>
#include <math.h>

// Dims
#define B_ 128
#define T_ 1024
#define I_ 256
#define H_ 512
#define O_ 256

typedef unsigned long long u64;
typedef ulonglong2 u64x2;

// Device scratch (static allocations are allowed)
__device__ __align__(16) float gW1t[768 * 512];   // [k][n] k:0..511 = h-k (Whh0), 512..767 = x-k (Wih0)
__device__ __align__(16) float gW2t[512 * 512];   // [k][n]  (Wih1+Whh1, transposed)
__device__ __align__(16) float gW3t[512 * 256];   // [k][o]  (Wout transposed)
__device__ __align__(16) float g_h1[B_ * H_];
__device__ __align__(16) float g_h2[B_ * H_];

// ---------- f32x2 helpers ----------
__device__ __forceinline__ u64 pack2(float x, float y) {
    u64 r; asm("mov.b64 %0,{%1,%2};" : "=l"(r) : "f"(x), "f"(y)); return r;
}
__device__ __forceinline__ void unpack2(u64 p, float& x, float& y) {
    asm("mov.b64 {%0,%1},%2;" : "=f"(x), "=f"(y) : "l"(p));
}
__device__ __forceinline__ u64 fma2_(u64 a, u64 b, u64 c) {
    u64 d; asm("fma.rn.f32x2 %0,%1,%2,%3;" : "=l"(d) : "l"(a), "l"(b), "l"(c)); return d;
}
__device__ __forceinline__ u64 add2_(u64 a, u64 b) {
    u64 d; asm("add.rn.f32x2 %0,%1,%2;" : "=l"(d) : "l"(a), "l"(b)); return d;
}
__device__ __forceinline__ float mytanh(float x) {
    float xc = fminf(12.f, fmaxf(-12.f, x));
    float e = __expf(2.f * xc);
    return __fdividef(e - 1.f, e + 1.f);
}
__device__ __forceinline__ void cluster_bar() {
    asm volatile("barrier.cluster.arrive.aligned;" ::: "memory");
    asm volatile("barrier.cluster.wait.aligned;" ::: "memory");
}

// ---------- SMEM layout (float offsets) ----------
// W2S  : [0, 32768)           512 x 64  Wc slice, k-major
// AS   : [32768, 45184)       u64[8][776]  activation staging, DUPLICATED pairs: AS[m][k] = (v,v)
// SCR  : [45184, 49280)       u64[2048]    A/B split-K scratch
// SCRC : [49280, 51328)       u64[1024]    C split-K scratch
// b0s  : [51328, 51392)  bcs : [51392, 51456)  bos : [51456, 51488)
#define W2S_OFF  0
#define AS_OFF   32768
#define SCR_OFF  45184
#define SCRC_OFF 49280
#define B0_OFF   51328
#define BC_OFF   51392
#define BO_OFF   51456
#define SMEM_FLOATS 51488
#define SMEM_BYTES (SMEM_FLOATS * 4)
#define AS_STRIDE 776   // u64 per m row (768 k + pad)

// ---------- prep kernel: transpose / combine weights ----------
__global__ void rnn_prep(const float* __restrict__ Wih0, const float* __restrict__ Whh0,
                         const float* __restrict__ Wih1, const float* __restrict__ Whh1,
                         const float* __restrict__ Wout) {
    int i = blockIdx.x * blockDim.x + threadIdx.x;
    if (i < 768 * 512) {
        int k = i >> 9, n = i & 511;
        gW1t[i] = (k < 512) ? Whh0[n * 512 + k] : Wih0[n * 256 + (k - 512)];
    }
    if (i < 512 * 512) {
        int k = i >> 9, n = i & 511;
        gW2t[i] = Wih1[n * 512 + k] + Whh1[n * 512 + k];
    }
    if (i < 512 * 256) {
        int k = i >> 8, o = i & 255;
        gW3t[i] = Wout[o * 512 + k];
    }
}

// ---------- staging: global h (8 rows x 512) -> AS duplicated ----------
__device__ __forceinline__ void stage_h(u64* AS, const float* src, int grp8, int tid) {
    int m = tid >> 6, cu = tid & 63;
    const u64* row = reinterpret_cast<const u64*>(src + (size_t)(grp8 + m) * 512);
    u64* dst = AS + m * AS_STRIDE;
#pragma unroll
    for (int i = 0; i < 4; i++) {
        int w = cu + 64 * i;                 // u64 word index (coalesced per instr)
        u64 v = __ldcg(row + w);
        float v0, v1; unpack2(v, v0, v1);
        dst[2 * w]     = pack2(v0, v0);
        dst[2 * w + 1] = pack2(v1, v1);
    }
}
__device__ __forceinline__ void stage_x(u64* AS, const float* x, int grp8, int t, int tid) {
    int m = tid >> 6, cu = tid & 63;
    const u64* row = reinterpret_cast<const u64*>(x + ((size_t)(grp8 + m) * T_ + t) * I_);
    u64* dst = AS + m * AS_STRIDE + 512;
#pragma unroll
    for (int i = 0; i < 2; i++) {
        int w = cu + 64 * i;
        u64 v = __ldg(row + w);
        float v0, v1; unpack2(v, v0, v1);
        dst[2 * w]     = pack2(v0, v0);
        dst[2 * w + 1] = pack2(v1, v1);
    }
}

// ---------- main persistent kernel ----------
__global__ void __launch_bounds__(512, 1) __cluster_dims__(8, 1, 1)
rnn_main(const float* __restrict__ x, const float* __restrict__ h0,
         const float* __restrict__ bih0, const float* __restrict__ bhh0,
         const float* __restrict__ bih1, const float* __restrict__ bhh1,
         const float* __restrict__ bout, float* __restrict__ out) {
    extern __shared__ float smem[];
    float* W2S = smem + W2S_OFF;
    u64*   AS   = reinterpret_cast<u64*>(smem + AS_OFF);
    u64*   SCR  = reinterpret_cast<u64*>(smem + SCR_OFF);
    u64*   SCRC = reinterpret_cast<u64*>(smem + SCRC_OFF);
    float* b0s = smem + B0_OFF;
    float* bcs = smem + BC_OFF;
    float* bos = smem + BO_OFF;

    const int tid  = threadIdx.x;
    const int grp  = blockIdx.x >> 3;     // 16 batch groups
    const int rank = blockIdx.x & 7;      // column slice within cluster
    const int grp8 = grp * 8;
    const int nb = rank * 64;             // hidden col base
    const int ob = rank * 32;             // output col base

    const int ks = tid >> 6;              // split-K part 0..7
    const int m8 = (tid >> 3) & 7;        // batch row within group
    const int cg = tid & 7;               // col-group (8 cols for A/B, 4 for C)

    // ---- resident weight slice + biases ----
    for (int i = tid; i < 512 * 64; i += 512) {
        int k = i >> 6, j = i & 63;
        W2S[i] = gW2t[k * 512 + nb + j];
    }
    if (tid < 64) b0s[tid] = bih0[nb + tid] + bhh0[nb + tid];
    if (tid < 64) bcs[tid] = bih1[nb + tid] + bhh1[nb + tid];
    if (tid < 32) bos[tid] = bout[ob + tid];

    stage_h(AS, h0, grp8, tid);
    stage_x(AS, x, grp8, 0, tid);
    __syncthreads();

    const float* W1base = gW1t + nb + cg * 8;
    const float* W3base = gW3t + ob + cg * 4;
    const u64*   actA   = AS + m8 * AS_STRIDE;

    for (int t = 0; t < T_; t++) {
        // ================= Phase A: h1 = tanh([h;x] @ W1^T + b0) =================
        u64 a0 = 0, a1 = 0, a2 = 0, a3 = 0;
        {
            const float* wp = W1base + (size_t)(ks * 96) * 512;
            const u64*   ap = actA + ks * 96;
#pragma unroll 1
            for (int blk = 0; blk < 12; blk++) {
                u64x2 w[8][2];
#pragma unroll
                for (int i = 0; i < 8; i++) {
                    w[i][0] = *reinterpret_cast<const u64x2*>(wp + (size_t)i * 512);
                    w[i][1] = *reinterpret_cast<const u64x2*>(wp + (size_t)i * 512 + 4);
                }
#pragma unroll
                for (int i = 0; i < 8; i++) {
                    u64 a = ap[i];
                    a0 = fma2_(a, w[i][0].x, a0);
                    a1 = fma2_(a, w[i][0].y, a1);
                    a2 = fma2_(a, w[i][1].x, a2);
                    a3 = fma2_(a, w[i][1].y, a3);
                }
                wp += 8 * 512; ap += 8;
            }
        }
        __syncthreads();
        SCR[tid * 4 + 0] = a0; SCR[tid * 4 + 1] = a1;
        SCR[tid * 4 + 2] = a2; SCR[tid * 4 + 3] = a3;
        __syncthreads();
        if (tid < 256) {
            int m = tid >> 5, cp = tid & 31;
            u64 s = SCR[m * 32 + cp];
#pragma unroll
            for (int k2 = 1; k2 < 8; k2++) s = add2_(s, SCR[k2 * 256 + m * 32 + cp]);
            int col = ((cp >> 2) << 3) + ((cp & 3) << 1);
            s = add2_(s, *reinterpret_cast<const u64*>(b0s + col));
            float v0, v1; unpack2(s, v0, v1);
            v0 = mytanh(v0); v1 = mytanh(v1);
            *reinterpret_cast<u64*>(&g_h1[(grp8 + m) * 512 + nb + col]) = pack2(v0, v1);
            __threadfence();
        }
        cluster_bar();  // exchange h1

        stage_h(AS, g_h1, grp8, tid);
        __syncthreads();

        // ================= Phase B: h2 = tanh(h1 @ Wc^T + bc) =================
        a0 = 0; a1 = 0; a2 = 0; a3 = 0;
        {
            const float* wp = W2S + (ks * 64) * 64 + cg * 8;
            const u64*   ap = actA + ks * 64;
#pragma unroll 8
            for (int i = 0; i < 64; i++) {
                u64x2 w0 = *reinterpret_cast<const u64x2*>(wp + i * 64);
                u64x2 w1 = *reinterpret_cast<const u64x2*>(wp + i * 64 + 4);
                u64 a = ap[i];
                a0 = fma2_(a, w0.x, a0);
                a1 = fma2_(a, w0.y, a1);
                a2 = fma2_(a, w1.x, a2);
                a3 = fma2_(a, w1.y, a3);
            }
        }
        __syncthreads();
        SCR[tid * 4 + 0] = a0; SCR[tid * 4 + 1] = a1;
        SCR[tid * 4 + 2] = a2; SCR[tid * 4 + 3] = a3;
        __syncthreads();
        if (tid < 256) {
            int m = tid >> 5, cp = tid & 31;
            u64 s = SCR[m * 32 + cp];
#pragma unroll
            for (int k2 = 1; k2 < 8; k2++) s = add2_(s, SCR[k2 * 256 + m * 32 + cp]);
            int col = ((cp >> 2) << 3) + ((cp & 3) << 1);
            s = add2_(s, *reinterpret_cast<const u64*>(bcs + col));
            float v0, v1; unpack2(s, v0, v1);
            v0 = mytanh(v0); v1 = mytanh(v1);
            *reinterpret_cast<u64*>(&g_h2[(grp8 + m) * 512 + nb + col]) = pack2(v0, v1);
            __threadfence();
        }
        cluster_bar();  // exchange h2 (feeds phase C and next step's phase A)

        stage_h(AS, g_h2, grp8, tid);
        int tn = (t + 1 < T_) ? (t + 1) : t;
        stage_x(AS, x, grp8, tn, tid);
        __syncthreads();

        // ================= Phase C: y = h2 @ Wout^T + b_out =================
        u64 c0 = 0, c1 = 0;
        {
            const float* wp = W3base + (size_t)(ks * 64) * 256;
            const u64*   ap = actA + ks * 64;
#pragma unroll 1
            for (int blk = 0; blk < 8; blk++) {
                u64x2 w[8];
#pragma unroll
                for (int i = 0; i < 8; i++)
                    w[i] = *reinterpret_cast<const u64x2*>(wp + (size_t)i * 256);
#pragma unroll
                for (int i = 0; i < 8; i++) {
                    u64 a = ap[i];
                    c0 = fma2_(a, w[i].x, c0);
                    c1 = fma2_(a, w[i].y, c1);
                }
                wp += 8 * 256; ap += 8;
            }
        }
        __syncthreads();
        SCRC[tid * 2 + 0] = c0; SCRC[tid * 2 + 1] = c1;
        __syncthreads();
        if (tid < 128) {
            int m = tid >> 4, cp = tid & 15;
            u64 s = SCRC[m * 16 + cp];
#pragma unroll
            for (int k2 = 1; k2 < 8; k2++) s = add2_(s, SCRC[k2 * 128 + m * 16 + cp]);
            int col = ((cp >> 1) << 2) + ((cp & 1) << 1);
            s = add2_(s, *reinterpret_cast<const u64*>(bos + col));
            *reinterpret_cast<u64*>(
                &out[(size_t)(grp8 + m) * (T_ * O_) + (size_t)t * O_ + ob + col]) = s;
        }
        // no extra sync: next phase-A reads only AS (stable); SCR rewrite is
        // guarded by the sync after the next A k-loop.
    }
}

extern "C" void kernel_launch(void* const* d_in, const int* in_sizes, int n_in,
                              void* d_out, int out_size) {
    const float* x    = (const float*)d_in[0];
    const float* h0   = (const float*)d_in[1];
    const float* Wih0 = (const float*)d_in[2];
    const float* bih0 = (const float*)d_in[3];
    const float* Whh0 = (const float*)d_in[4];
    const float* bhh0 = (const float*)d_in[5];
    const float* Wih1 = (const float*)d_in[6];
    const float* bih1 = (const float*)d_in[7];
    const float* Whh1 = (const float*)d_in[8];
    const float* bhh1 = (const float*)d_in[9];
    const float* Wout = (const float*)d_in[10];
    const float* bout = (const float*)d_in[11];
    float* out = (float*)d_out;

    cudaFuncSetAttribute(rnn_main, cudaFuncAttributeMaxDynamicSharedMemorySize, SMEM_BYTES);

    rnn_prep<<<(768 * 512 + 255) / 256, 256>>>(Wih0, Whh0, Wih1, Whh1, Wout);
    rnn_main<<<128, 512, SMEM_BYTES>>>(x, h0, bih0, bhh0, bih1, bhh1, bout, out);
}

// round 8
// speedup vs baseline: 1.4852x; 1.4852x over previous
#include <cuda_runtime.h>
#include <stdint.h>
#include <math.h>

// Dims
#define B_ 128
#define T_ 1024
#define I_ 256
#define H_ 512
#define O_ 256

typedef unsigned long long u64;
typedef ulonglong2 u64x2;

// k-pair interleaved weights: idx = kp2*W*2 + col*2 + kbit
__device__ __align__(16) float gW1i[384 * 1024];  // [kp2][c<512][kb]  k<512:h, k>=512:x
__device__ __align__(16) float gW2i[256 * 1024];  // [kp2][c<512][kb]  (Wih1+Whh1)
__device__ __align__(16) float gW3i[256 * 512];   // [kp2][o<256][kb]  (Wout)

// ---------- f32x2 helpers ----------
__device__ __forceinline__ void unpack2(u64 p, float& x, float& y) {
    asm("mov.b64 {%0,%1},%2;" : "=f"(x), "=f"(y) : "l"(p));
}
__device__ __forceinline__ u64 fma2_(u64 a, u64 b, u64 c) {
    u64 d; asm("fma.rn.f32x2 %0,%1,%2,%3;" : "=l"(d) : "l"(a), "l"(b), "l"(c)); return d;
}
__device__ __forceinline__ u64 add2_(u64 a, u64 b) {
    u64 d; asm("add.rn.f32x2 %0,%1,%2;" : "=l"(d) : "l"(a), "l"(b)); return d;
}
__device__ __forceinline__ float mytanh(float x) {
    float xc = fminf(12.f, fmaxf(-12.f, x));
    float e = __expf(2.f * xc);
    return __fdividef(e - 1.f, e + 1.f);
}
__device__ __forceinline__ void cluster_bar() {
    asm volatile("barrier.cluster.arrive.aligned;" ::: "memory");
    asm volatile("barrier.cluster.wait.aligned;" ::: "memory");
}
// store v into the SAME smem offset of all 8 cluster CTAs
__device__ __forceinline__ void publish8(uint32_t loc, float v) {
#pragma unroll
    for (int r = 0; r < 8; r++) {
        uint32_t rem;
        asm("mapa.shared::cluster.u32 %0, %1, %2;" : "=r"(rem) : "r"(loc), "r"(r));
        asm volatile("st.shared::cluster.f32 [%0], %1;" :: "r"(rem), "f"(v) : "memory");
    }
}

// ---------- SMEM layout (float offsets) ----------
// W2S: [0,32768)  interleaved Wc slice [kp2][c_local<64][kb]
// ASA: [32768,38976)  float[8][776]  per m: k<512 = h, 512..767 = x   (compact)
// ASB: [38976,43136)  float[8][520]  h1 buffer
// SCR: [43136,45184)  u64[1024] split-K scratch
// biases: b0s/bcs/bos
#define W2S_OFF 0
#define ASA_OFF 32768
#define ASB_OFF 38976
#define SCR_OFF 43136
#define B0_OFF  45184
#define BC_OFF  45248
#define BO_OFF  45312
#define SMEM_FLOATS 45344
#define SMEM_BYTES (SMEM_FLOATS * 4)
#define ASA_STRIDE 776
#define ASB_STRIDE 520

// ---------- prep: build k-pair interleaved weights ----------
__global__ void rnn_prep(const float* __restrict__ Wih0, const float* __restrict__ Whh0,
                         const float* __restrict__ Wih1, const float* __restrict__ Whh1,
                         const float* __restrict__ Wout) {
    int i = blockIdx.x * blockDim.x + threadIdx.x;
    if (i < 384 * 1024) {
        int kp2 = i >> 10, r = i & 1023, c = r >> 1, kb = r & 1;
        int k = 2 * kp2 + kb;
        gW1i[i] = (k < 512) ? Whh0[c * 512 + k] : Wih0[c * 256 + (k - 512)];
    }
    if (i < 256 * 1024) {
        int kp2 = i >> 10, r = i & 1023, c = r >> 1, kb = r & 1;
        int k = 2 * kp2 + kb;
        gW2i[i] = Wih1[c * 512 + k] + Whh1[c * 512 + k];
    }
    if (i < 256 * 512) {
        int kp2 = i >> 9, r = i & 511, o = r >> 1, kb = r & 1;
        int k = 2 * kp2 + kb;
        gW3i[i] = Wout[o * 512 + k];
    }
}

// ---------- main persistent kernel ----------
__global__ void __launch_bounds__(512, 1) __cluster_dims__(8, 1, 1)
rnn_main(const float* __restrict__ x, const float* __restrict__ h0,
         const float* __restrict__ bih0, const float* __restrict__ bhh0,
         const float* __restrict__ bih1, const float* __restrict__ bhh1,
         const float* __restrict__ bout, float* __restrict__ out) {
    extern __shared__ float smem[];
    float* W2S = smem + W2S_OFF;
    float* ASA = smem + ASA_OFF;
    float* ASB = smem + ASB_OFF;
    u64*   SCR = reinterpret_cast<u64*>(smem + SCR_OFF);
    float* b0s = smem + B0_OFF;
    float* bcs = smem + BC_OFF;
    float* bos = smem + BO_OFF;

    const int tid  = threadIdx.x;
    const int lane = tid & 31;
    const int wrp  = tid >> 5;
    const int m_w  = wrp & 7;    // warp's batch row (within group of 8)
    const int ks   = wrp >> 3;   // 2-way split-K
    const int grp8 = (blockIdx.x >> 3) * 8;
    const int rank = blockIdx.x & 7;
    const int nb = rank * 64;    // hidden col base (A/B output slice)
    const int ob = rank * 32;    // output col base

    uint32_t smem_u32;
    asm("{ .reg .u64 t; cvta.to.shared.u64 t, %1; cvt.u32.u64 %0, t; }"
        : "=r"(smem_u32) : "l"(smem));
    const uint32_t asa_u32 = smem_u32 + ASA_OFF * 4;
    const uint32_t asb_u32 = smem_u32 + ASB_OFF * 4;

    // ---- init: W2 slice into SMEM (interleaved rows are contiguous 128-float chunks) ----
    for (int i = tid; i < 32768; i += 512) {
        int kp2 = i >> 7, rem = i & 127;
        W2S[i] = gW2i[kp2 * 1024 + nb * 2 + rem];
    }
    if (tid < 64)       b0s[tid] = bih0[nb + tid] + bhh0[nb + tid];
    else if (tid < 128) { int c = tid - 64; bcs[c] = bih1[nb + c] + bhh1[nb + c]; }
    else if (tid < 160) { int c = tid - 128; bos[c] = bout[ob + c]; }

    {   // stage h0 + x0 compact
        int sm0 = tid >> 6, sq0 = tid & 63;
        const float4* hsrc = reinterpret_cast<const float4*>(h0 + (size_t)(grp8 + sm0) * H_);
        *reinterpret_cast<float4*>(ASA + sm0 * ASA_STRIDE + sq0 * 4)        = __ldg(hsrc + sq0);
        *reinterpret_cast<float4*>(ASA + sm0 * ASA_STRIDE + (sq0 + 64) * 4) = __ldg(hsrc + sq0 + 64);
        const float4* xsrc = reinterpret_cast<const float4*>(x + (size_t)(grp8 + sm0) * T_ * I_);
        *reinterpret_cast<float4*>(ASA + sm0 * ASA_STRIDE + 512 + sq0 * 4)  = __ldg(xsrc + sq0);
    }
    __syncthreads();
    cluster_bar();

    // hot-loop base pointers
    const u64x2* wpA = reinterpret_cast<const u64x2*>(gW1i)
                       + (size_t)(ks * 192) * 256 + (nb >> 1) + lane;   // row = 256 u64x2
    const u64*   apA = reinterpret_cast<const u64*>(ASA + m_w * ASA_STRIDE + ks * 384);
    const u64x2* wpB = reinterpret_cast<const u64x2*>(W2S) + ks * 128 * 32 + lane;  // row = 32 u64x2
    const u64*   apB = reinterpret_cast<const u64*>(ASB + m_w * ASB_STRIDE + ks * 256);
    const u64*   wpC = reinterpret_cast<const u64*>(gW3i)
                       + (size_t)(ks * 128) * 256 + ob + lane;          // row = 256 u64
    const u64*   apC = reinterpret_cast<const u64*>(ASA + m_w * ASA_STRIDE + ks * 256);

    const int rm = tid >> 6, rc = tid & 63;   // A/B reducer: (m, col)
    const int cm = tid >> 5, cc = tid & 31;   // C reducer  : (m, col), tid<256
    const int sm = tid >> 6, sq = tid & 63;   // x stager

    for (int t = 0; t < T_; t++) {
        // ============ Phase A: h1 = tanh([h;x] @ W1^T + b0) ============
        u64 a0 = 0, a1 = 0;
        {
            const u64x2* wq = wpA;
            const u64*   aq = apA;
            u64x2 w[2][4]; u64 a[2][4];
#pragma unroll
            for (int i = 0; i < 4; i++) { w[0][i] = wq[(size_t)i * 256]; a[0][i] = aq[i]; }
            wq += 4 * 256; aq += 4;
#pragma unroll 2
            for (int blk = 0; blk < 48; blk++) {
                int cur = blk & 1, nxt = cur ^ 1;
                if (blk < 47) {
#pragma unroll
                    for (int i = 0; i < 4; i++) { w[nxt][i] = wq[(size_t)i * 256]; a[nxt][i] = aq[i]; }
                    wq += 4 * 256; aq += 4;
                }
#pragma unroll
                for (int i = 0; i < 4; i++) {
                    a0 = fma2_(a[cur][i], w[cur][i].x, a0);
                    a1 = fma2_(a[cur][i], w[cur][i].y, a1);
                }
            }
        }
        __syncthreads();  // (a) all AS reads + prev SCR reads done
        *reinterpret_cast<u64x2*>(&SCR[ks * 512 + m_w * 64 + 2 * lane]) = make_ulonglong2(a0, a1);
        {   // stage x_{t+1} (A finished reading x_t)
            int tn = (t + 1 < T_) ? (t + 1) : t;
            const float4* xsrc =
                reinterpret_cast<const float4*>(x + ((size_t)(grp8 + sm) * T_ + tn) * I_);
            *reinterpret_cast<float4*>(ASA + sm * ASA_STRIDE + 512 + sq * 4) = __ldg(xsrc + sq);
        }
        __syncthreads();  // (b)
        {
            u64 s = add2_(SCR[rm * 64 + rc], SCR[512 + rm * 64 + rc]);
            float e, o; unpack2(s, e, o);
            float v = mytanh(e + o + b0s[rc]);
            publish8(asb_u32 + (uint32_t)(rm * ASB_STRIDE + nb + rc) * 4u, v);
        }
        cluster_bar();   // #1: h1 visible in every CTA's ASB

        // ============ Phase B: h2 = tanh(h1 @ Wc^T + bc) ============
        a0 = 0; a1 = 0;
        {
#pragma unroll 1
            for (int blk = 0; blk < 16; blk++) {
                u64x2 w[8]; u64 a[8];
#pragma unroll
                for (int i = 0; i < 8; i++) {
                    w[i] = wpB[(blk * 8 + i) * 32];
                    a[i] = apB[blk * 8 + i];
                }
#pragma unroll
                for (int i = 0; i < 8; i++) {
                    a0 = fma2_(a[i], w[i].x, a0);
                    a1 = fma2_(a[i], w[i].y, a1);
                }
            }
        }
        // prev SCR readers all finished before cbar#1 — safe to write without sync
        *reinterpret_cast<u64x2*>(&SCR[ks * 512 + m_w * 64 + 2 * lane]) = make_ulonglong2(a0, a1);
        __syncthreads();  // (d)
        {
            u64 s = add2_(SCR[rm * 64 + rc], SCR[512 + rm * 64 + rc]);
            float e, o; unpack2(s, e, o);
            float v = mytanh(e + o + bcs[rc]);
            publish8(asa_u32 + (uint32_t)(rm * ASA_STRIDE + nb + rc) * 4u, v);
        }
        cluster_bar();   // #2: h2 visible in every CTA's ASA (h region)

        // ============ Phase C: y_t = h2 @ Wout^T + b_out ============
        u64 c0 = 0;
        {
            const u64* wq = wpC;
            const u64* aq = apC;
            u64 w[2][4]; u64 a[2][4];
#pragma unroll
            for (int i = 0; i < 4; i++) { w[0][i] = wq[(size_t)i * 256]; a[0][i] = aq[i]; }
            wq += 4 * 256; aq += 4;
#pragma unroll 2
            for (int blk = 0; blk < 32; blk++) {
                int cur = blk & 1, nxt = cur ^ 1;
                if (blk < 31) {
#pragma unroll
                    for (int i = 0; i < 4; i++) { w[nxt][i] = wq[(size_t)i * 256]; a[nxt][i] = aq[i]; }
                    wq += 4 * 256; aq += 4;
                }
#pragma unroll
                for (int i = 0; i < 4; i++) c0 = fma2_(a[cur][i], w[cur][i], c0);
            }
        }
        SCR[ks * 256 + m_w * 32 + lane] = c0;  // prev readers done before cbar#2
        __syncthreads();  // (f)
        if (tid < 256) {
            u64 s = add2_(SCR[cm * 32 + cc], SCR[256 + cm * 32 + cc]);
            float e, o; unpack2(s, e, o);
            out[(size_t)(grp8 + cm) * (T_ * O_) + (size_t)t * O_ + ob + cc] = e + o + bos[cc];
        }
        // next iteration's sync (a) guards SCR rewrite vs these reads
    }
}

extern "C" void kernel_launch(void* const* d_in, const int* in_sizes, int n_in,
                              void* d_out, int out_size) {
    const float* x    = (const float*)d_in[0];
    const float* h0   = (const float*)d_in[1];
    const float* Wih0 = (const float*)d_in[2];
    const float* bih0 = (const float*)d_in[3];
    const float* Whh0 = (const float*)d_in[4];
    const float* bhh0 = (const float*)d_in[5];
    const float* Wih1 = (const float*)d_in[6];
    const float* bih1 = (const float*)d_in[7];
    const float* Whh1 = (const float*)d_in[8];
    const float* bhh1 = (const float*)d_in[9];
    const float* Wout = (const float*)d_in[10];
    const float* bout = (const float*)d_in[11];
    float* out = (float*)d_out;

    cudaFuncSetAttribute(rnn_main, cudaFuncAttributeMaxDynamicSharedMemorySize, SMEM_BYTES);

    rnn_prep<<<1536, 256>>>(Wih0, Whh0, Wih1, Whh1, Wout);
    rnn_main<<<128, 512, SMEM_BYTES>>>(x, h0, bih0, bhh0, bih1, bhh1, bout, out);
}

// round 9
// speedup vs baseline: 2.7843x; 1.8747x over previous
#include <cuda_runtime.h>
#include <stdint.h>
#include <math.h>

// Dims
#define B_ 128
#define T_ 1024
#define I_ 256
#define H_ 512
#define O_ 256

typedef unsigned long long u64;
typedef ulonglong2 u64x2;

// k-pair interleaved weights: idx = kp2*(ncols*2) + col*2 + kbit
__device__ __align__(16) float gW1i[384 * 1024];  // [kp2][c<512][kb]  k<512:h, k>=512:x
__device__ __align__(16) float gW2i[256 * 1024];  // [kp2][c<512][kb]  (Wih1+Whh1)
__device__ __align__(16) float gW3i[256 * 512];   // [kp2][o<256][kb]  (Wout)

// ---------- f32x2 helpers ----------
__device__ __forceinline__ void unpack2(u64 p, float& x, float& y) {
    asm("mov.b64 {%0,%1},%2;" : "=f"(x), "=f"(y) : "l"(p));
}
__device__ __forceinline__ u64 fma2_(u64 a, u64 b, u64 c) {
    u64 d; asm("fma.rn.f32x2 %0,%1,%2,%3;" : "=l"(d) : "l"(a), "l"(b), "l"(c)); return d;
}
__device__ __forceinline__ u64 add2_(u64 a, u64 b) {
    u64 d; asm("add.rn.f32x2 %0,%1,%2;" : "=l"(d) : "l"(a), "l"(b)); return d;
}
__device__ __forceinline__ float mytanh(float x) {
    float xc = fminf(12.f, fmaxf(-12.f, x));
    float e = __expf(2.f * xc);
    return __fdividef(e - 1.f, e + 1.f);
}
__device__ __forceinline__ void cluster_bar() {
    asm volatile("barrier.cluster.arrive.aligned;" ::: "memory");
    asm volatile("barrier.cluster.wait.aligned;" ::: "memory");
}
__device__ __forceinline__ uint32_t mapa_rank(uint32_t loc, int r) {
    uint32_t rem;
    asm("mapa.shared::cluster.u32 %0, %1, %2;" : "=r"(rem) : "r"(loc), "r"(r));
    return rem;
}
__device__ __forceinline__ void st_remote(uint32_t addr, float v) {
    asm volatile("st.shared::cluster.f32 [%0], %1;" :: "r"(addr), "f"(v) : "memory");
}

// ---------- SMEM layout (float offsets) ----------
// ASTA: [0,6144)      u64[8][384]  per m: kp2 0..255 = h, 256..383 = x
// ASB : [6144,10240)  u64[8][256]  h1 buffer
// SCR : [10240,26624) u64[8192]    16-way split-K scratch
// b0s : 26624  bcs : 26688  bos : 26752
#define ASTA_OFF 0
#define ASB_OFF  6144
#define SCR_OFF  10240
#define B0_OFF   26624
#define BC_OFF   26688
#define BO_OFF   26752
#define SMEM_FLOATS 26784
#define SMEM_BYTES (SMEM_FLOATS * 4)

// ---------- prep: build k-pair interleaved weights ----------
__global__ void rnn_prep(const float* __restrict__ Wih0, const float* __restrict__ Whh0,
                         const float* __restrict__ Wih1, const float* __restrict__ Whh1,
                         const float* __restrict__ Wout) {
    int i = blockIdx.x * blockDim.x + threadIdx.x;
    if (i < 384 * 1024) {
        int kp2 = i >> 10, r = i & 1023, c = r >> 1, kb = r & 1;
        int k = 2 * kp2 + kb;
        gW1i[i] = (k < 512) ? Whh0[c * 512 + k] : Wih0[c * 256 + (k - 512)];
    }
    if (i < 256 * 1024) {
        int kp2 = i >> 10, r = i & 1023, c = r >> 1, kb = r & 1;
        int k = 2 * kp2 + kb;
        gW2i[i] = Wih1[c * 512 + k] + Whh1[c * 512 + k];
    }
    if (i < 256 * 512) {
        int kp2 = i >> 9, r = i & 511, o = r >> 1, kb = r & 1;
        int k = 2 * kp2 + kb;
        gW3i[i] = Wout[o * 512 + k];
    }
}

// ---------- main persistent kernel ----------
__global__ void __launch_bounds__(512, 1) __cluster_dims__(8, 1, 1)
rnn_main(const float* __restrict__ x, const float* __restrict__ h0,
         const float* __restrict__ bih0, const float* __restrict__ bhh0,
         const float* __restrict__ bih1, const float* __restrict__ bhh1,
         const float* __restrict__ bout, float* __restrict__ out) {
    extern __shared__ float smem[];
    u64*   ASTA = reinterpret_cast<u64*>(smem + ASTA_OFF);  // [m][384]
    u64*   ASB  = reinterpret_cast<u64*>(smem + ASB_OFF);   // [m][256]
    u64*   SCR  = reinterpret_cast<u64*>(smem + SCR_OFF);
    float* b0s = smem + B0_OFF;
    float* bcs = smem + BC_OFF;
    float* bos = smem + BO_OFF;

    const int tid  = threadIdx.x;
    const int lane = tid & 31;
    const int ws   = tid >> 5;   // warp = 16-way split-K slice
    const int grp8 = (blockIdx.x >> 3) * 8;
    const int rank = blockIdx.x & 7;
    const int nb = rank * 64;    // hidden col base (A/B output slice)
    const int ob = rank * 32;    // output col base

    uint32_t smem_u32;
    asm("{ .reg .u64 t; cvta.to.shared.u64 t, %1; cvt.u32.u64 %0, t; }"
        : "=r"(smem_u32) : "l"(smem));

    // ---- biases ----
    if (tid < 64)       b0s[tid] = bih0[nb + tid] + bhh0[nb + tid];
    else if (tid < 128) { int c = tid - 64; bcs[c] = bih1[nb + c] + bhh1[nb + c]; }
    else if (tid < 160) { int c = tid - 128; bos[c] = bout[ob + c]; }

    // ---- initial staging: h0 (full 512 cols) + x0 per m row ----
    const int sm_ = tid >> 6, q = tid & 63;
    {
        float4* f4A = reinterpret_cast<float4*>(ASTA);  // 192 float4 per m
        const float4* hsrc = reinterpret_cast<const float4*>(h0 + (size_t)(grp8 + sm_) * H_);
        f4A[sm_ * 192 + q]      = __ldg(hsrc + q);
        f4A[sm_ * 192 + 64 + q] = __ldg(hsrc + q + 64);
        const float4* xsrc = reinterpret_cast<const float4*>(x + (size_t)(grp8 + sm_) * T_ * I_);
        f4A[sm_ * 192 + 128 + q] = __ldg(xsrc + q);
    }

    // ---- reducer publish targets (hoisted mapa) ----
    const int rm = tid >> 6, rc = tid & 63;   // A/B reducer: (m, col-offset)
    const int col = nb + rc;
    uint32_t remA[8], remB[8];
    {
        uint32_t locA = smem_u32 + (uint32_t)((ASTA_OFF) * 4 + (rm * 384 + (col >> 1)) * 8 + (col & 1) * 4);
        uint32_t locB = smem_u32 + (uint32_t)((ASB_OFF) * 4 + (rm * 256 + (col >> 1)) * 8 + (col & 1) * 4);
#pragma unroll
        for (int r = 0; r < 8; r++) { remA[r] = mapa_rank(locA, r); remB[r] = mapa_rank(locB, r); }
    }

    __syncthreads();
    cluster_bar();

    // ---- hot-loop base pointers ----
    const u64x2* wA = reinterpret_cast<const u64x2*>(gW1i) + (size_t)(ws * 24) * 256 + rank * 32 + lane;
    const u64x2* wB = reinterpret_cast<const u64x2*>(gW2i) + (size_t)(ws * 16) * 256 + rank * 32 + lane;
    const u64*   wC = reinterpret_cast<const u64*>(gW3i)   + (size_t)(ws * 16) * 256 + ob + lane;
    const u64x2* aA = reinterpret_cast<const u64x2*>(ASTA) + ws * 12;  // + m*192 + blk
    const u64x2* aB = reinterpret_cast<const u64x2*>(ASB)  + ws * 8;   // + m*128 + blk
    const u64x2* aC = reinterpret_cast<const u64x2*>(ASTA) + ws * 8;   // + m*192 + blk

    // A/B reducer read base: SCR[ws2*512 + (m*2 + (c&1))*32 + (c>>1)]
    const int redAB = (rm * 2 + (rc & 1)) * 32 + (rc >> 1);
    // C reducer (tid<256): SCR[ws2*256 + m*32 + c]
    const int cmm = tid >> 5, ccc = tid & 31;

    for (int t = 0; t < T_; t++) {
        // ============ Phase A: h1 = tanh([h;x] @ W1^T + b0) ============
        u64 acc[8][2];
#pragma unroll
        for (int m = 0; m < 8; m++) { acc[m][0] = 0; acc[m][1] = 0; }
        {
            u64x2 w0 = wA[0], w1 = wA[256];
#pragma unroll 4
            for (int blk = 0; blk < 12; blk++) {
                u64x2 w0n, w1n;
                if (blk < 11) { w0n = wA[(size_t)(2 * blk + 2) * 256]; w1n = wA[(size_t)(2 * blk + 3) * 256]; }
#pragma unroll
                for (int m = 0; m < 8; m++) {
                    u64x2 a2 = aA[m * 192 + blk];
                    acc[m][0] = fma2_(a2.x, w0.x, acc[m][0]);
                    acc[m][1] = fma2_(a2.x, w0.y, acc[m][1]);
                    acc[m][0] = fma2_(a2.y, w1.x, acc[m][0]);
                    acc[m][1] = fma2_(a2.y, w1.y, acc[m][1]);
                }
                w0 = w0n; w1 = w1n;
            }
        }
        __syncthreads();  // (a): A reads of AST done; prev C-reducer SCR reads done
#pragma unroll
        for (int m = 0; m < 8; m++) {
            SCR[ws * 512 + (m * 2 + 0) * 32 + lane] = acc[m][0];
            SCR[ws * 512 + (m * 2 + 1) * 32 + lane] = acc[m][1];
        }
        {   // stage x_{t+1}
            int tn = (t + 1 < T_) ? (t + 1) : t;
            float4* f4A = reinterpret_cast<float4*>(ASTA);
            const float4* xsrc =
                reinterpret_cast<const float4*>(x + ((size_t)(grp8 + sm_) * T_ + tn) * I_);
            f4A[sm_ * 192 + 128 + q] = __ldg(xsrc + q);
        }
        __syncthreads();  // (b)
        {   // reduce 16-way, tanh, publish h1 to all ranks' ASB
            u64 s = SCR[redAB];
#pragma unroll
            for (int w2 = 1; w2 < 16; w2++) s = add2_(s, SCR[w2 * 512 + redAB]);
            float e, o; unpack2(s, e, o);
            float v = mytanh(e + o + b0s[rc]);
#pragma unroll
            for (int r = 0; r < 8; r++) st_remote(remB[r], v);
        }
        cluster_bar();   // #1: h1 complete in every CTA's ASB

        // ============ Phase B: h2 = tanh(h1 @ Wc^T + bc) ============
#pragma unroll
        for (int m = 0; m < 8; m++) { acc[m][0] = 0; acc[m][1] = 0; }
        {
            u64x2 w0 = wB[0], w1 = wB[256];
#pragma unroll 4
            for (int blk = 0; blk < 8; blk++) {
                u64x2 w0n, w1n;
                if (blk < 7) { w0n = wB[(size_t)(2 * blk + 2) * 256]; w1n = wB[(size_t)(2 * blk + 3) * 256]; }
#pragma unroll
                for (int m = 0; m < 8; m++) {
                    u64x2 a2 = aB[m * 128 + blk];
                    acc[m][0] = fma2_(a2.x, w0.x, acc[m][0]);
                    acc[m][1] = fma2_(a2.x, w0.y, acc[m][1]);
                    acc[m][0] = fma2_(a2.y, w1.x, acc[m][0]);
                    acc[m][1] = fma2_(a2.y, w1.y, acc[m][1]);
                }
                w0 = w0n; w1 = w1n;
            }
        }
        // prev SCR readers (A reducers) finished before cbar#1 — safe to write
#pragma unroll
        for (int m = 0; m < 8; m++) {
            SCR[ws * 512 + (m * 2 + 0) * 32 + lane] = acc[m][0];
            SCR[ws * 512 + (m * 2 + 1) * 32 + lane] = acc[m][1];
        }
        __syncthreads();  // (d)
        {   // reduce, tanh, publish h2 to all ranks' ASTA h-region
            u64 s = SCR[redAB];
#pragma unroll
            for (int w2 = 1; w2 < 16; w2++) s = add2_(s, SCR[w2 * 512 + redAB]);
            float e, o; unpack2(s, e, o);
            float v = mytanh(e + o + bcs[rc]);
#pragma unroll
            for (int r = 0; r < 8; r++) st_remote(remA[r], v);
        }
        cluster_bar();   // #2: h2 complete everywhere (feeds C and next A)

        // ============ Phase C: y_t = h2 @ Wout^T + b_out ============
        u64 accc[8];
#pragma unroll
        for (int m = 0; m < 8; m++) accc[m] = 0;
        {
            u64 w0 = wC[0], w1 = wC[256];
#pragma unroll 4
            for (int blk = 0; blk < 8; blk++) {
                u64 w0n, w1n;
                if (blk < 7) { w0n = wC[(size_t)(2 * blk + 2) * 256]; w1n = wC[(size_t)(2 * blk + 3) * 256]; }
#pragma unroll
                for (int m = 0; m < 8; m++) {
                    u64x2 a2 = aC[m * 192 + blk];
                    accc[m] = fma2_(a2.x, w0, accc[m]);
                    accc[m] = fma2_(a2.y, w1, accc[m]);
                }
                w0 = w0n; w1 = w1n;
            }
        }
        // prev SCR readers (B reducers) finished before cbar#2 — safe
#pragma unroll
        for (int m = 0; m < 8; m++) SCR[ws * 256 + m * 32 + lane] = accc[m];
        __syncthreads();  // (f)
        if (tid < 256) {
            u64 s = SCR[cmm * 32 + ccc];
#pragma unroll
            for (int w2 = 1; w2 < 16; w2++) s = add2_(s, SCR[w2 * 256 + cmm * 32 + ccc]);
            float e, o; unpack2(s, e, o);
            out[(size_t)(grp8 + cmm) * (T_ * O_) + (size_t)t * O_ + ob + ccc] = e + o + bos[ccc];
        }
        // next step's sync (a) guards SCR rewrite vs these reads
    }
}

extern "C" void kernel_launch(void* const* d_in, const int* in_sizes, int n_in,
                              void* d_out, int out_size) {
    const float* x    = (const float*)d_in[0];
    const float* h0   = (const float*)d_in[1];
    const float* Wih0 = (const float*)d_in[2];
    const float* bih0 = (const float*)d_in[3];
    const float* Whh0 = (const float*)d_in[4];
    const float* bhh0 = (const float*)d_in[5];
    const float* Wih1 = (const float*)d_in[6];
    const float* bih1 = (const float*)d_in[7];
    const float* Whh1 = (const float*)d_in[8];
    const float* bhh1 = (const float*)d_in[9];
    const float* Wout = (const float*)d_in[10];
    const float* bout = (const float*)d_in[11];
    float* out = (float*)d_out;

    cudaFuncSetAttribute(rnn_main, cudaFuncAttributeMaxDynamicSharedMemorySize, SMEM_BYTES);

    rnn_prep<<<1536, 256>>>(Wih0, Whh0, Wih1, Whh1, Wout);
    rnn_main<<<128, 512, SMEM_BYTES>>>(x, h0, bih0, bhh0, bih1, bhh1, bout, out);
}

// round 10
// speedup vs baseline: 2.9211x; 1.0491x over previous
#include <cuda_runtime.h>
#include <stdint.h>
#include <math.h>

// Dims
#define B_ 128
#define T_ 1024
#define I_ 256
#define H_ 512
#define O_ 256

typedef unsigned long long u64;
typedef ulonglong2 u64x2;

// k-pair interleaved weights: idx = kp2*(ncols*2) + col*2 + kbit
__device__ __align__(16) float gW1i[384 * 1024];  // [kp2][c<512][kb]  k<512:h, k>=512:x
__device__ __align__(16) float gW2i[256 * 1024];  // [kp2][c<512][kb]  (Wih1+Whh1)
__device__ __align__(16) float gW3i[256 * 512];   // [kp2][o<256][kb]  (Wout)

// ---------- f32x2 helpers ----------
__device__ __forceinline__ void unpack2(u64 p, float& x, float& y) {
    asm("mov.b64 {%0,%1},%2;" : "=f"(x), "=f"(y) : "l"(p));
}
__device__ __forceinline__ u64 fma2_(u64 a, u64 b, u64 c) {
    u64 d; asm("fma.rn.f32x2 %0,%1,%2,%3;" : "=l"(d) : "l"(a), "l"(b), "l"(c)); return d;
}
__device__ __forceinline__ u64 add2_(u64 a, u64 b) {
    u64 d; asm("add.rn.f32x2 %0,%1,%2;" : "=l"(d) : "l"(a), "l"(b)); return d;
}
__device__ __forceinline__ float mytanh(float x) {
    float xc = fminf(12.f, fmaxf(-12.f, x));
    float e = __expf(2.f * xc);
    return __fdividef(e - 1.f, e + 1.f);
}
__device__ __forceinline__ void cluster_bar() {
    asm volatile("barrier.cluster.arrive.aligned;" ::: "memory");
    asm volatile("barrier.cluster.wait.aligned;" ::: "memory");
}
__device__ __forceinline__ void st_remote_rank(uint32_t loc, int r, float v) {
    uint32_t rem;
    asm("mapa.shared::cluster.u32 %0, %1, %2;" : "=r"(rem) : "r"(loc), "r"(r));
    asm volatile("st.shared::cluster.f32 [%0], %1;" :: "r"(rem), "f"(v) : "memory");
}

// ---------- SMEM layout (float offsets) ----------
// ASTA: [0,6144)      u64[8][384]  per m: kp2 0..255 = h, 256..383 = x
// ASB : [6144,10240)  u64[8][256]  h1 buffer
// SCR : [10240,26624) u64[8192]    16-way split-K scratch
// b0s : 26624  bcs : 26688  bos : 26752
#define ASTA_OFF 0
#define ASB_OFF  6144
#define SCR_OFF  10240
#define B0_OFF   26624
#define BC_OFF   26688
#define BO_OFF   26752
#define SMEM_FLOATS 26784
#define SMEM_BYTES (SMEM_FLOATS * 4)

// ---------- prep: build k-pair interleaved weights ----------
__global__ void rnn_prep(const float* __restrict__ Wih0, const float* __restrict__ Whh0,
                         const float* __restrict__ Wih1, const float* __restrict__ Whh1,
                         const float* __restrict__ Wout) {
    int i = blockIdx.x * blockDim.x + threadIdx.x;
    if (i < 384 * 1024) {
        int kp2 = i >> 10, r = i & 1023, c = r >> 1, kb = r & 1;
        int k = 2 * kp2 + kb;
        gW1i[i] = (k < 512) ? Whh0[c * 512 + k] : Wih0[c * 256 + (k - 512)];
    }
    if (i < 256 * 1024) {
        int kp2 = i >> 10, r = i & 1023, c = r >> 1, kb = r & 1;
        int k = 2 * kp2 + kb;
        gW2i[i] = Wih1[c * 512 + k] + Whh1[c * 512 + k];
    }
    if (i < 256 * 512) {
        int kp2 = i >> 9, r = i & 511, o = r >> 1, kb = r & 1;
        int k = 2 * kp2 + kb;
        gW3i[i] = Wout[o * 512 + k];
    }
}

// ---------- main persistent kernel ----------
__global__ void __launch_bounds__(512, 1) __cluster_dims__(8, 1, 1)
rnn_main(const float* __restrict__ x, const float* __restrict__ h0,
         const float* __restrict__ bih0, const float* __restrict__ bhh0,
         const float* __restrict__ bih1, const float* __restrict__ bhh1,
         const float* __restrict__ bout, float* __restrict__ out) {
    extern __shared__ float smem[];
    u64*   ASTA = reinterpret_cast<u64*>(smem + ASTA_OFF);  // [m][384]
    u64*   SCR  = reinterpret_cast<u64*>(smem + SCR_OFF);
    float* b0s = smem + B0_OFF;
    float* bcs = smem + BC_OFF;
    float* bos = smem + BO_OFF;

    const int tid  = threadIdx.x;
    const int lane = tid & 31;
    const int ws   = tid >> 5;   // warp = 16-way split-K slice
    const int grp8 = (blockIdx.x >> 3) * 8;
    const int rank = blockIdx.x & 7;
    const int nb = rank * 64;    // hidden col base (A/B output slice)
    const int ob = rank * 32;    // output col base

    uint32_t smem_u32;
    asm("{ .reg .u64 t; cvta.to.shared.u64 t, %1; cvt.u32.u64 %0, t; }"
        : "=r"(smem_u32) : "l"(smem));

    // ---- biases ----
    if (tid < 64)       b0s[tid] = bih0[nb + tid] + bhh0[nb + tid];
    else if (tid < 128) { int c = tid - 64; bcs[c] = bih1[nb + c] + bhh1[nb + c]; }
    else if (tid < 160) { int c = tid - 128; bos[c] = bout[ob + c]; }

    // ---- initial staging: h0 (full 512 cols) + x0 per m row ----
    const int sm_ = tid >> 6, q = tid & 63;
    {
        float4* f4A = reinterpret_cast<float4*>(ASTA);  // 96 float4 per m in h region of 192
        const float4* hsrc = reinterpret_cast<const float4*>(h0 + (size_t)(grp8 + sm_) * H_);
        f4A[sm_ * 192 + q]      = __ldg(hsrc + q);
        f4A[sm_ * 192 + 64 + q] = __ldg(hsrc + q + 64);
        const float4* xsrc = reinterpret_cast<const float4*>(x + (size_t)(grp8 + sm_) * T_ * I_);
        f4A[sm_ * 192 + 128 + q] = __ldg(xsrc + q);
    }

    // ---- reducer indices ----
    const int rm = tid >> 6, rc = tid & 63;   // A/B reducer: (m, col-offset)
    const int col = nb + rc;
    const uint32_t locB = smem_u32 + (uint32_t)(ASB_OFF * 4 + ((rm * 256 + (col >> 1)) * 8 + (col & 1) * 4));
    const uint32_t locA = smem_u32 + (uint32_t)(ASTA_OFF * 4 + ((rm * 384 + (col >> 1)) * 8 + (col & 1) * 4));

    __syncthreads();
    cluster_bar();

    // ---- hot-loop base pointers ----
    const u64x2* wA = reinterpret_cast<const u64x2*>(gW1i) + (size_t)(ws * 24) * 256 + rank * 32 + lane;
    const u64x2* wB = reinterpret_cast<const u64x2*>(gW2i) + (size_t)(ws * 16) * 256 + rank * 32 + lane;
    const u64*   wC = reinterpret_cast<const u64*>(gW3i)   + (size_t)(ws * 16) * 256 + ob + lane;
    const u64x2* aA = reinterpret_cast<const u64x2*>(ASTA) + ws * 12;                 // + m*192 + blk
    const u64x2* aB = reinterpret_cast<const u64x2*>(smem + ASB_OFF) + ws * 8;        // + m*128 + blk
    const u64x2* aC = reinterpret_cast<const u64x2*>(ASTA) + ws * 8;                  // + m*192 + blk

    const int redAB = (rm * 2 + (rc & 1)) * 32 + (rc >> 1);
    const int cmm = tid >> 5, ccc = tid & 31;

    // persistent A prefetch buffer (depth 2 blocks = 4 kp2)
    u64x2 pwA[2][2];
    pwA[0][0] = wA[0];   pwA[0][1] = wA[256];
    pwA[1][0] = wA[512]; pwA[1][1] = wA[768];

    for (int t = 0; t < T_; t++) {
        // x_{t+1} prefetch into registers (lands during phase A)
        int tn = (t + 1 < T_) ? (t + 1) : t;
        float4 xr = __ldg(reinterpret_cast<const float4*>(
            x + ((size_t)(grp8 + sm_) * T_ + tn) * I_) + q);

        // ============ Phase A: h1 = tanh([h;x] @ W1^T + b0) ============
        u64 acc[8][2];
#pragma unroll
        for (int m = 0; m < 8; m++) { acc[m][0] = 0; acc[m][1] = 0; }
#pragma unroll
        for (int blk = 0; blk < 12; blk++) {
            const int s = blk & 1;
            u64x2 w0 = pwA[s][0], w1 = pwA[s][1];
            if (blk < 10) {
                pwA[s][0] = wA[(size_t)(2 * blk + 4) * 256];
                pwA[s][1] = wA[(size_t)(2 * blk + 5) * 256];
            }
#pragma unroll
            for (int m = 0; m < 8; m++) {
                u64x2 a2 = aA[m * 192 + blk];
                acc[m][0] = fma2_(a2.x, w0.x, acc[m][0]);
                acc[m][1] = fma2_(a2.x, w0.y, acc[m][1]);
                acc[m][0] = fma2_(a2.y, w1.x, acc[m][0]);
                acc[m][1] = fma2_(a2.y, w1.y, acc[m][1]);
            }
        }
        __syncthreads();  // (a): AST reads done; prev C-reducer SCR reads done
#pragma unroll
        for (int m = 0; m < 8; m++) {
            SCR[ws * 512 + (m * 2 + 0) * 32 + lane] = acc[m][0];
            SCR[ws * 512 + (m * 2 + 1) * 32 + lane] = acc[m][1];
        }
        {   // stage x_{t+1} from registers (no latency here)
            float4* f4A = reinterpret_cast<float4*>(ASTA);
            f4A[sm_ * 192 + 128 + q] = xr;
        }
        __syncthreads();  // (b)
        {   // reduce 16-way, tanh, publish h1 to all ranks' ASB
            u64 s = SCR[redAB];
#pragma unroll
            for (int w2 = 1; w2 < 16; w2++) s = add2_(s, SCR[w2 * 512 + redAB]);
            float e, o; unpack2(s, e, o);
            float v = mytanh(e + o + b0s[rc]);
#pragma unroll
            for (int r = 0; r < 8; r++) st_remote_rank(locB, r, v);
        }
        // preload B stages (independent of h1) — overlaps bar wait
        u64x2 pwB[2][2];
        pwB[0][0] = wB[0];   pwB[0][1] = wB[256];
        pwB[1][0] = wB[512]; pwB[1][1] = wB[768];
        cluster_bar();   // #1: h1 complete in every CTA's ASB

        // ============ Phase B: h2 = tanh(h1 @ Wc^T + bc) ============
#pragma unroll
        for (int m = 0; m < 8; m++) { acc[m][0] = 0; acc[m][1] = 0; }
#pragma unroll
        for (int blk = 0; blk < 8; blk++) {
            const int s = blk & 1;
            u64x2 w0 = pwB[s][0], w1 = pwB[s][1];
            if (blk < 6) {
                pwB[s][0] = wB[(size_t)(2 * blk + 4) * 256];
                pwB[s][1] = wB[(size_t)(2 * blk + 5) * 256];
            }
#pragma unroll
            for (int m = 0; m < 8; m++) {
                u64x2 a2 = aB[m * 128 + blk];
                acc[m][0] = fma2_(a2.x, w0.x, acc[m][0]);
                acc[m][1] = fma2_(a2.x, w0.y, acc[m][1]);
                acc[m][0] = fma2_(a2.y, w1.x, acc[m][0]);
                acc[m][1] = fma2_(a2.y, w1.y, acc[m][1]);
            }
        }
        // prev SCR readers (A reducers) finished before cbar#1 — safe to write
#pragma unroll
        for (int m = 0; m < 8; m++) {
            SCR[ws * 512 + (m * 2 + 0) * 32 + lane] = acc[m][0];
            SCR[ws * 512 + (m * 2 + 1) * 32 + lane] = acc[m][1];
        }
        __syncthreads();  // (d)
        {   // reduce, tanh, publish h2 to all ranks' ASTA h-region
            u64 s = SCR[redAB];
#pragma unroll
            for (int w2 = 1; w2 < 16; w2++) s = add2_(s, SCR[w2 * 512 + redAB]);
            float e, o; unpack2(s, e, o);
            float v = mytanh(e + o + bcs[rc]);
#pragma unroll
            for (int r = 0; r < 8; r++) st_remote_rank(locA, r, v);
        }
        // preload C stages (independent of h2) — overlaps bar wait
        u64 pwC[2][2];
        pwC[0][0] = wC[0];   pwC[0][1] = wC[256];
        pwC[1][0] = wC[512]; pwC[1][1] = wC[768];
        cluster_bar();   // #2: h2 complete everywhere (feeds C and next A)

        // ============ Phase C: y_t = h2 @ Wout^T + b_out ============
        u64 accc[8];
#pragma unroll
        for (int m = 0; m < 8; m++) accc[m] = 0;
#pragma unroll
        for (int blk = 0; blk < 8; blk++) {
            const int s = blk & 1;
            u64 w0 = pwC[s][0], w1 = pwC[s][1];
            if (blk < 6) {
                pwC[s][0] = wC[(size_t)(2 * blk + 4) * 256];
                pwC[s][1] = wC[(size_t)(2 * blk + 5) * 256];
            }
#pragma unroll
            for (int m = 0; m < 8; m++) {
                u64x2 a2 = aC[m * 192 + blk];
                accc[m] = fma2_(a2.x, w0, accc[m]);
                accc[m] = fma2_(a2.y, w1, accc[m]);
            }
        }
        // prev SCR readers (B reducers) finished before cbar#2 — safe
#pragma unroll
        for (int m = 0; m < 8; m++) SCR[ws * 256 + m * 32 + lane] = accc[m];
        // preload next-step A stages (independent data) — lands across sync(f)+epilogue
        pwA[0][0] = wA[0];   pwA[0][1] = wA[256];
        pwA[1][0] = wA[512]; pwA[1][1] = wA[768];
        __syncthreads();  // (f)
        if (tid < 256) {
            u64 s = SCR[cmm * 32 + ccc];
#pragma unroll
            for (int w2 = 1; w2 < 16; w2++) s = add2_(s, SCR[w2 * 256 + cmm * 32 + ccc]);
            float e, o; unpack2(s, e, o);
            out[(size_t)(grp8 + cmm) * (T_ * O_) + (size_t)t * O_ + ob + ccc] = e + o + bos[ccc];
        }
        // next step's sync (a) guards SCR rewrite vs these reads
    }
}

extern "C" void kernel_launch(void* const* d_in, const int* in_sizes, int n_in,
                              void* d_out, int out_size) {
    const float* x    = (const float*)d_in[0];
    const float* h0   = (const float*)d_in[1];
    const float* Wih0 = (const float*)d_in[2];
    const float* bih0 = (const float*)d_in[3];
    const float* Whh0 = (const float*)d_in[4];
    const float* bhh0 = (const float*)d_in[5];
    const float* Wih1 = (const float*)d_in[6];
    const float* bih1 = (const float*)d_in[7];
    const float* Whh1 = (const float*)d_in[8];
    const float* bhh1 = (const float*)d_in[9];
    const float* Wout = (const float*)d_in[10];
    const float* bout = (const float*)d_in[11];
    float* out = (float*)d_out;

    cudaFuncSetAttribute(rnn_main, cudaFuncAttributeMaxDynamicSharedMemorySize, SMEM_BYTES);

    rnn_prep<<<1536, 256>>>(Wih0, Whh0, Wih1, Whh1, Wout);
    rnn_main<<<128, 512, SMEM_BYTES>>>(x, h0, bih0, bhh0, bih1, bhh1, bout, out);
}

// round 11
// speedup vs baseline: 3.7404x; 1.2805x over previous
#include <cuda_runtime.h>
#include <stdint.h>
#include <math.h>

// Dims
#define B_ 128
#define T_ 1024
#define I_ 256
#define H_ 512
#define O_ 256

typedef unsigned long long u64;
typedef ulonglong2 u64x2;

// k-pair interleaved weights: idx = kp2*(ncols*2) + col*2 + kbit
__device__ __align__(16) float gW1i[384 * 1024];  // [kp2][c<512][kb]  k<512:h, k>=512:x
__device__ __align__(16) float gW2i[256 * 1024];  // [kp2][c<512][kb]  (Wih1+Whh1)
__device__ __align__(16) float gW3i[256 * 512];   // [kp2][o<256][kb]  (Wout)

// ---------- helpers ----------
__device__ __forceinline__ u64 pack2(float x, float y) {
    u64 r; asm("mov.b64 %0,{%1,%2};" : "=l"(r) : "f"(x), "f"(y)); return r;
}
__device__ __forceinline__ void unpack2(u64 p, float& x, float& y) {
    asm("mov.b64 {%0,%1},%2;" : "=f"(x), "=f"(y) : "l"(p));
}
__device__ __forceinline__ u64 fma2_(u64 a, u64 b, u64 c) {
    u64 d; asm("fma.rn.f32x2 %0,%1,%2,%3;" : "=l"(d) : "l"(a), "l"(b), "l"(c)); return d;
}
__device__ __forceinline__ u64 add2_(u64 a, u64 b) {
    u64 d; asm("add.rn.f32x2 %0,%1,%2;" : "=l"(d) : "l"(a), "l"(b)); return d;
}
__device__ __forceinline__ float mytanh(float x) {
    float xc = fminf(12.f, fmaxf(-12.f, x));
    float e = __expf(2.f * xc);
    return __fdividef(e - 1.f, e + 1.f);
}
__device__ __forceinline__ void cluster_bar() {
    asm volatile("barrier.cluster.arrive.aligned;" ::: "memory");
    asm volatile("barrier.cluster.wait.aligned;" ::: "memory");
}
__device__ __forceinline__ uint32_t mapa_u32(uint32_t loc, int r) {
    uint32_t rem;
    asm("mapa.shared::cluster.u32 %0, %1, %2;" : "=r"(rem) : "r"(loc), "r"(r));
    return rem;
}
// remote 8-byte store with transaction accounting on the target CTA's mbarrier
__device__ __forceinline__ void st_async64(uint32_t dst, u64 v, uint32_t mbar) {
    asm volatile("st.async.shared::cluster.mbarrier::complete_tx::bytes.b64 [%0], %1, [%2];"
                 :: "r"(dst), "l"(v), "r"(mbar) : "memory");
}
__device__ __forceinline__ void mbar_init(uint32_t mbar, uint32_t count) {
    asm volatile("mbarrier.init.shared.b64 [%0], %1;" :: "r"(mbar), "r"(count) : "memory");
}
__device__ __forceinline__ void mbar_arm(uint32_t mbar, uint32_t tx) {
    asm volatile("mbarrier.arrive.expect_tx.shared.b64 _, [%0], %1;" :: "r"(mbar), "r"(tx) : "memory");
}
__device__ __forceinline__ void mbar_wait(uint32_t mbar, uint32_t parity) {
    uint32_t done;
    asm volatile(
        "{\n\t.reg .pred p;\n\t"
        "mbarrier.try_wait.parity.acquire.cta.shared::cta.b64 p, [%1], %2;\n\t"
        "selp.b32 %0, 1, 0, p;\n\t}"
        : "=r"(done) : "r"(mbar), "r"(parity) : "memory");
    if (!done) {
        asm volatile(
            "{\n\t.reg .pred P1;\n\t"
            "WAIT_LOOP_%=:\n\t"
            "mbarrier.try_wait.parity.acquire.cta.shared::cta.b64 P1, [%0], %1, 0x989680;\n\t"
            "@P1 bra.uni WAIT_DONE_%=;\n\t"
            "bra.uni WAIT_LOOP_%=;\n\t"
            "WAIT_DONE_%=:\n\t}"
            :: "r"(mbar), "r"(parity) : "memory");
    }
}

// ---------- SMEM layout (float offsets) ----------
// W2S : [0,32768)        interleaved Wc slice [kp2][c_local 64][kb]   128 KB
// ASTA: [32768,38912)    u64[8][384]  per m: kp2 0..255 = h2, 256..383 = x   24 KB
// ASB : [38912,43008)    u64[8][256]  h1 buffer                              16 KB
// SCRF: [43008,51200)    f32[16][8][64] split-K partials (C aliases first half) 32 KB
// bias: b0s 51200  bcs 51264  bos 51328
// mbar: mbB 51360  mbA 51362
#define W2S_OFF  0
#define ASTA_OFF 32768
#define ASB_OFF  38912
#define SCRF_OFF 43008
#define B0_OFF   51200
#define BC_OFF   51264
#define BO_OFF   51328
#define MBB_OFF  51360
#define MBA_OFF  51362
#define SMEM_FLOATS 51364
#define SMEM_BYTES (SMEM_FLOATS * 4)
#define TX_BYTES 16384u   // full h (8 m x 512 cols x 4B) received per CTA per exchange

// ---------- prep: build k-pair interleaved weights ----------
__global__ void rnn_prep(const float* __restrict__ Wih0, const float* __restrict__ Whh0,
                         const float* __restrict__ Wih1, const float* __restrict__ Whh1,
                         const float* __restrict__ Wout) {
    int i = blockIdx.x * blockDim.x + threadIdx.x;
    if (i < 384 * 1024) {
        int kp2 = i >> 10, r = i & 1023, c = r >> 1, kb = r & 1;
        int k = 2 * kp2 + kb;
        gW1i[i] = (k < 512) ? Whh0[c * 512 + k] : Wih0[c * 256 + (k - 512)];
    }
    if (i < 256 * 1024) {
        int kp2 = i >> 10, r = i & 1023, c = r >> 1, kb = r & 1;
        int k = 2 * kp2 + kb;
        gW2i[i] = Wih1[c * 512 + k] + Whh1[c * 512 + k];
    }
    if (i < 256 * 512) {
        int kp2 = i >> 9, r = i & 511, o = r >> 1, kb = r & 1;
        int k = 2 * kp2 + kb;
        gW3i[i] = Wout[o * 512 + k];
    }
}

// ---------- main persistent kernel ----------
__global__ void __launch_bounds__(512, 1) __cluster_dims__(8, 1, 1)
rnn_main(const float* __restrict__ x, const float* __restrict__ h0,
         const float* __restrict__ bih0, const float* __restrict__ bhh0,
         const float* __restrict__ bih1, const float* __restrict__ bhh1,
         const float* __restrict__ bout, float* __restrict__ out) {
    extern __shared__ float smem[];
    float* W2S  = smem + W2S_OFF;
    u64*   ASTA = reinterpret_cast<u64*>(smem + ASTA_OFF);  // [m][384]
    float* SCRF = smem + SCRF_OFF;
    float* b0s = smem + B0_OFF;
    float* bcs = smem + BC_OFF;
    float* bos = smem + BO_OFF;

    const int tid  = threadIdx.x;
    const int lane = tid & 31;
    const int ws   = tid >> 5;   // warp = 16-way split-K slice
    const int grp8 = (blockIdx.x >> 3) * 8;
    const int rank = blockIdx.x & 7;
    const int nb = rank * 64;    // hidden col base
    const int ob = rank * 32;    // output col base

    uint32_t smem_u32;
    asm("{ .reg .u64 t; cvta.to.shared.u64 t, %1; cvt.u32.u64 %0, t; }"
        : "=r"(smem_u32) : "l"(smem));
    const uint32_t mbB_loc = smem_u32 + MBB_OFF * 4;
    const uint32_t mbA_loc = smem_u32 + MBA_OFF * 4;

    // ---- biases ----
    if (tid < 64)       b0s[tid] = bih0[nb + tid] + bhh0[nb + tid];
    else if (tid < 128) { int c = tid - 64; bcs[c] = bih1[nb + c] + bhh1[nb + c]; }
    else if (tid < 160) { int c = tid - 128; bos[c] = bout[ob + c]; }

    // ---- W2 slice into SMEM (interleaved rows contiguous per kp2) ----
    for (int i = tid; i < 32768; i += 512) {
        int kp2 = i >> 7, rem = i & 127;
        W2S[i] = gW2i[kp2 * 1024 + rank * 128 + rem];
    }

    // ---- initial staging: h0 + x0 ----
    const int sm_ = tid >> 6, q = tid & 63;
    {
        float4* f4A = reinterpret_cast<float4*>(ASTA);  // 192 float4 per m
        const float4* hsrc = reinterpret_cast<const float4*>(h0 + (size_t)(grp8 + sm_) * H_);
        f4A[sm_ * 192 + q]      = __ldg(hsrc + q);
        f4A[sm_ * 192 + 64 + q] = __ldg(hsrc + q + 64);
        const float4* xsrc = reinterpret_cast<const float4*>(x + (size_t)(grp8 + sm_) * T_ * I_);
        f4A[sm_ * 192 + 128 + q] = __ldg(xsrc + q);
    }

    // ---- mbar init + arm mbB for step 0 ----
    if (tid == 0) {
        mbar_init(mbB_loc, 1);
        mbar_init(mbA_loc, 1);
        mbar_arm(mbB_loc, TX_BYTES);
    }
    __syncthreads();
    cluster_bar();   // once: mbars + SMEM visible cluster-wide before any st.async

    // ---- hot-loop base pointers ----
    const u64x2* wA  = reinterpret_cast<const u64x2*>(gW1i) + (size_t)(ws * 24) * 256 + rank * 32 + lane;
    const u64x2* wBs = reinterpret_cast<const u64x2*>(W2S) + ws * 16 * 32 + lane;     // row = 32 u64x2
    const u64*   wC  = reinterpret_cast<const u64*>(gW3i)  + (size_t)(ws * 16) * 256 + ob + lane;
    const u64x2* aA  = reinterpret_cast<const u64x2*>(ASTA) + ws * 12;                // + m*192 + blk
    const u64x2* aB  = reinterpret_cast<const u64x2*>(smem + ASB_OFF) + ws * 8;       // + m*128 + blk
    const u64x2* aC  = reinterpret_cast<const u64x2*>(ASTA) + ws * 8;                 // + m*192 + blk

    // reducer indices / publish targets (tid<256 for A/B, tid<128 for C)
    const int rm = tid >> 5, rc = tid & 31;          // (m, colpair) for A/B reduce
    const uint32_t dstB_loc = smem_u32 + (uint32_t)(ASB_OFF + rm * 512 + nb + 2 * rc) * 4u;
    const uint32_t dstA_loc = smem_u32 + (uint32_t)(ASTA_OFF + rm * 768 + nb + 2 * rc) * 4u;
    const int cm = tid >> 4, cc = tid & 15;          // (m, colpair) for C reduce

    // persistent A prefetch buffer (depth 2 blocks = 4 kp2)
    u64x2 pwA[2][2];
    pwA[0][0] = wA[0];   pwA[0][1] = wA[256];
    pwA[1][0] = wA[512]; pwA[1][1] = wA[768];

    for (int t = 0; t < T_; t++) {
        const uint32_t par = (uint32_t)(t & 1);
        // x_{t+1} prefetch into registers (lands during phase A)
        int tn = (t + 1 < T_) ? (t + 1) : t;
        float4 xr = __ldg(reinterpret_cast<const float4*>(
            x + ((size_t)(grp8 + sm_) * T_ + tn) * I_) + q);

        // ============ Phase A: h1 = tanh([h;x] @ W1^T + b0) ============
        u64 acc[8][2];
#pragma unroll
        for (int m = 0; m < 8; m++) { acc[m][0] = 0; acc[m][1] = 0; }
#pragma unroll
        for (int blk = 0; blk < 12; blk++) {
            const int s = blk & 1;
            u64x2 w0 = pwA[s][0], w1 = pwA[s][1];
            if (blk < 10) {
                pwA[s][0] = wA[(size_t)(2 * blk + 4) * 256];
                pwA[s][1] = wA[(size_t)(2 * blk + 5) * 256];
            }
#pragma unroll
            for (int m = 0; m < 8; m++) {
                u64x2 a2 = aA[m * 192 + blk];
                acc[m][0] = fma2_(a2.x, w0.x, acc[m][0]);
                acc[m][1] = fma2_(a2.x, w0.y, acc[m][1]);
                acc[m][0] = fma2_(a2.y, w1.x, acc[m][0]);
                acc[m][1] = fma2_(a2.y, w1.y, acc[m][1]);
            }
        }
        __syncthreads();  // (a): ASTA-x reads + prev C SCR reads done
        // combine k-parity pairs -> f32 partials
#pragma unroll
        for (int m = 0; m < 8; m++) {
            float e0, o0, e1, o1;
            unpack2(acc[m][0], e0, o0); unpack2(acc[m][1], e1, o1);
            *reinterpret_cast<float2*>(&SCRF[ws * 512 + m * 64 + 2 * lane]) =
                make_float2(e0 + o0, e1 + o1);
        }
        {   // stage x_{t+1} from registers
            float4* f4A = reinterpret_cast<float4*>(ASTA);
            f4A[sm_ * 192 + 128 + q] = xr;
        }
        if (tid == 0) mbar_arm(mbA_loc, TX_BYTES);   // arm h2-exchange for step t
        __syncthreads();  // (b)
        if (tid < 256) {  // reduce 16-way, tanh, publish h1 pairs to all ranks' ASB
            const float* base = SCRF + rm * 64 + 2 * rc;
            u64 s = *reinterpret_cast<const u64*>(base);
#pragma unroll
            for (int w2 = 1; w2 < 16; w2++)
                s = add2_(s, *reinterpret_cast<const u64*>(base + w2 * 512));
            s = add2_(s, *reinterpret_cast<const u64*>(b0s + 2 * rc));
            float e, o; unpack2(s, e, o);
            u64 v = pack2(mytanh(e), mytanh(o));
#pragma unroll
            for (int r = 0; r < 8; r++)
                st_async64(mapa_u32(dstB_loc, r), v, mapa_u32(mbB_loc, r));
        }
        mbar_wait(mbB_loc, par);   // h1 complete in my ASB; SCRF free (all senders done reading)

        // ============ Phase B: h2 = tanh(h1 @ Wc^T + bc) ============
#pragma unroll
        for (int m = 0; m < 8; m++) { acc[m][0] = 0; acc[m][1] = 0; }
#pragma unroll
        for (int blk = 0; blk < 8; blk++) {
            u64x2 w0 = wBs[(2 * blk) * 32];
            u64x2 w1 = wBs[(2 * blk + 1) * 32];
#pragma unroll
            for (int m = 0; m < 8; m++) {
                u64x2 a2 = aB[m * 128 + blk];
                acc[m][0] = fma2_(a2.x, w0.x, acc[m][0]);
                acc[m][1] = fma2_(a2.x, w0.y, acc[m][1]);
                acc[m][0] = fma2_(a2.y, w1.x, acc[m][0]);
                acc[m][1] = fma2_(a2.y, w1.y, acc[m][1]);
            }
        }
#pragma unroll
        for (int m = 0; m < 8; m++) {
            float e0, o0, e1, o1;
            unpack2(acc[m][0], e0, o0); unpack2(acc[m][1], e1, o1);
            *reinterpret_cast<float2*>(&SCRF[ws * 512 + m * 64 + 2 * lane]) =
                make_float2(e0 + o0, e1 + o1);
        }
        if (tid == 0) mbar_arm(mbB_loc, TX_BYTES);   // arm h1-exchange for step t+1
        __syncthreads();  // (d)
        if (tid < 256) {  // reduce, tanh, publish h2 pairs to all ranks' ASTA-h
            const float* base = SCRF + rm * 64 + 2 * rc;
            u64 s = *reinterpret_cast<const u64*>(base);
#pragma unroll
            for (int w2 = 1; w2 < 16; w2++)
                s = add2_(s, *reinterpret_cast<const u64*>(base + w2 * 512));
            s = add2_(s, *reinterpret_cast<const u64*>(bcs + 2 * rc));
            float e, o; unpack2(s, e, o);
            u64 v = pack2(mytanh(e), mytanh(o));
#pragma unroll
            for (int r = 0; r < 8; r++)
                st_async64(mapa_u32(dstA_loc, r), v, mapa_u32(mbA_loc, r));
        }
        // preload C weight stages (independent of h2) — overlaps wait
        u64 pwC[2][2];
        pwC[0][0] = wC[0];   pwC[0][1] = wC[256];
        pwC[1][0] = wC[512]; pwC[1][1] = wC[768];
        mbar_wait(mbA_loc, par);   // h2 complete everywhere (feeds C and next A); SCRF free

        // ============ Phase C: y_t = h2 @ Wout^T + b_out ============
        u64 accc[8];
#pragma unroll
        for (int m = 0; m < 8; m++) accc[m] = 0;
#pragma unroll
        for (int blk = 0; blk < 8; blk++) {
            const int s = blk & 1;
            u64 w0 = pwC[s][0], w1 = pwC[s][1];
            if (blk < 6) {
                pwC[s][0] = wC[(size_t)(2 * blk + 4) * 256];
                pwC[s][1] = wC[(size_t)(2 * blk + 5) * 256];
            }
#pragma unroll
            for (int m = 0; m < 8; m++) {
                u64x2 a2 = aC[m * 192 + blk];
                accc[m] = fma2_(a2.x, w0, accc[m]);
                accc[m] = fma2_(a2.y, w1, accc[m]);
            }
        }
#pragma unroll
        for (int m = 0; m < 8; m++) {   // combine -> f32, SCRC aliases SCRF[0..4096)
            float e, o; unpack2(accc[m], e, o);
            SCRF[ws * 256 + m * 32 + lane] = e + o;
        }
        // preload next-step A stages
        pwA[0][0] = wA[0];   pwA[0][1] = wA[256];
        pwA[1][0] = wA[512]; pwA[1][1] = wA[768];
        __syncthreads();  // (f)
        if (tid < 128) {
            const float* base = SCRF + cm * 32 + 2 * cc;
            u64 s = *reinterpret_cast<const u64*>(base);
#pragma unroll
            for (int w2 = 1; w2 < 16; w2++)
                s = add2_(s, *reinterpret_cast<const u64*>(base + w2 * 256));
            s = add2_(s, *reinterpret_cast<const u64*>(bos + 2 * cc));
            float e, o; unpack2(s, e, o);
            *reinterpret_cast<float2*>(
                &out[(size_t)(grp8 + cm) * (T_ * O_) + (size_t)t * O_ + ob + 2 * cc]) =
                make_float2(e, o);
        }
        // next step's sync (a) guards SCRC reads vs A-combine writes
    }
    cluster_bar();  // keep SMEM alive until all cluster traffic retired
}

extern "C" void kernel_launch(void* const* d_in, const int* in_sizes, int n_in,
                              void* d_out, int out_size) {
    const float* x    = (const float*)d_in[0];
    const float* h0   = (const float*)d_in[1];
    const float* Wih0 = (const float*)d_in[2];
    const float* bih0 = (const float*)d_in[3];
    const float* Whh0 = (const float*)d_in[4];
    const float* bhh0 = (const float*)d_in[5];
    const float* Wih1 = (const float*)d_in[6];
    const float* bih1 = (const float*)d_in[7];
    const float* Whh1 = (const float*)d_in[8];
    const float* bhh1 = (const float*)d_in[9];
    const float* Wout = (const float*)d_in[10];
    const float* bout = (const float*)d_in[11];
    float* out = (float*)d_out;

    cudaFuncSetAttribute(rnn_main, cudaFuncAttributeMaxDynamicSharedMemorySize, SMEM_BYTES);

    rnn_prep<<<1536, 256>>>(Wih0, Whh0, Wih1, Whh1, Wout);
    rnn_main<<<128, 512, SMEM_BYTES>>>(x, h0, bih0, bhh0, bih1, bhh1, bout, out);
}

// round 12
// speedup vs baseline: 3.7947x; 1.0145x over previous
#include <cuda_runtime.h>
#include <stdint.h>
#include <math.h>

// Dims
#define B_ 128
#define T_ 1024
#define I_ 256
#define H_ 512
#define O_ 256

typedef unsigned long long u64;
typedef ulonglong2 u64x2;

// k-pair interleaved weights: idx = kp2*(ncols*2) + col*2 + kbit
__device__ __align__(16) float gW1i[384 * 1024];  // [kp2][c<512][kb]  k<512:h, k>=512:x
__device__ __align__(16) float gW2i[256 * 1024];  // [kp2][c<512][kb]  (Wih1+Whh1)
__device__ __align__(16) float gW3i[256 * 512];   // [kp2][o<256][kb]  (Wout)

// ---------- helpers ----------
__device__ __forceinline__ u64 pack2(float x, float y) {
    u64 r; asm("mov.b64 %0,{%1,%2};" : "=l"(r) : "f"(x), "f"(y)); return r;
}
__device__ __forceinline__ void unpack2(u64 p, float& x, float& y) {
    asm("mov.b64 {%0,%1},%2;" : "=f"(x), "=f"(y) : "l"(p));
}
__device__ __forceinline__ u64 fma2_(u64 a, u64 b, u64 c) {
    u64 d; asm("fma.rn.f32x2 %0,%1,%2,%3;" : "=l"(d) : "l"(a), "l"(b), "l"(c)); return d;
}
__device__ __forceinline__ u64 add2_(u64 a, u64 b) {
    u64 d; asm("add.rn.f32x2 %0,%1,%2;" : "=l"(d) : "l"(a), "l"(b)); return d;
}
__device__ __forceinline__ float mytanh(float x) {
    float xc = fminf(12.f, fmaxf(-12.f, x));
    float e = __expf(2.f * xc);
    return __fdividef(e - 1.f, e + 1.f);
}
__device__ __forceinline__ void cluster_bar() {
    asm volatile("barrier.cluster.arrive.aligned;" ::: "memory");
    asm volatile("barrier.cluster.wait.aligned;" ::: "memory");
}
__device__ __forceinline__ uint32_t mapa_u32(uint32_t loc, int r) {
    uint32_t rem;
    asm("mapa.shared::cluster.u32 %0, %1, %2;" : "=r"(rem) : "r"(loc), "r"(r));
    return rem;
}
__device__ __forceinline__ void st_async64(uint32_t dst, u64 v, uint32_t mbar) {
    asm volatile("st.async.shared::cluster.mbarrier::complete_tx::bytes.b64 [%0], %1, [%2];"
                 :: "r"(dst), "l"(v), "r"(mbar) : "memory");
}
__device__ __forceinline__ void mbar_init(uint32_t mbar, uint32_t count) {
    asm volatile("mbarrier.init.shared.b64 [%0], %1;" :: "r"(mbar), "r"(count) : "memory");
}
__device__ __forceinline__ void mbar_arm(uint32_t mbar, uint32_t tx) {
    asm volatile("mbarrier.arrive.expect_tx.shared.b64 _, [%0], %1;" :: "r"(mbar), "r"(tx) : "memory");
}
__device__ __forceinline__ void mbar_wait(uint32_t mbar, uint32_t parity) {
    uint32_t done;
    asm volatile(
        "{\n\t.reg .pred p;\n\t"
        "mbarrier.try_wait.parity.acquire.cta.shared::cta.b64 p, [%1], %2;\n\t"
        "selp.b32 %0, 1, 0, p;\n\t}"
        : "=r"(done) : "r"(mbar), "r"(parity) : "memory");
    if (!done) {
        asm volatile(
            "{\n\t.reg .pred P1;\n\t"
            "WAIT_LOOP_%=:\n\t"
            "mbarrier.try_wait.parity.acquire.cta.shared::cta.b64 P1, [%0], %1, 0x989680;\n\t"
            "@P1 bra.uni WAIT_DONE_%=;\n\t"
            "bra.uni WAIT_LOOP_%=;\n\t"
            "WAIT_DONE_%=:\n\t}"
            :: "r"(mbar), "r"(parity) : "memory");
    }
}

// ---------- SMEM layout (float offsets) ----------
// W2S : [0,32768)        Wc slice [kp2][c_local 64][kb]              128 KB
// AST : [32768,38912)    u64[8][384]  per m: kp2 0..255=h2, 256..383=x  24 KB
// ASB : [38912,43008)    u64[8][256]  h1 buffer                      16 KB
// SCR : [43008,51200)    union: SCRA f32[12][512] + SCRC f32[4][256] | SCRB f32[16][512]
// bias: b0s 51200  bcs 51264  bos 51328
// mbar: mbB_lo 51360  mbB_hi 51362  mbA_lo 51364  mbA_hi 51366
#define AST_OFF  32768
#define ASB_OFF  38912
#define SCR_OFF  43008
#define SCRC_REL 6144
#define B0_OFF   51200
#define BC_OFF   51264
#define BO_OFF   51328
#define MBB_LO   51360
#define MBB_HI   51362
#define MBA_LO   51364
#define MBA_HI   51366
#define SMEM_FLOATS 51368
#define SMEM_BYTES (SMEM_FLOATS * 4)
#define TX_HALF 8192u    // 4 ranks x 8m x 64cols x 4B per half exchange

// ---------- prep: build k-pair interleaved weights ----------
__global__ void rnn_prep(const float* __restrict__ Wih0, const float* __restrict__ Whh0,
                         const float* __restrict__ Wih1, const float* __restrict__ Whh1,
                         const float* __restrict__ Wout) {
    int i = blockIdx.x * blockDim.x + threadIdx.x;
    if (i < 384 * 1024) {
        int kp2 = i >> 10, r = i & 1023, c = r >> 1, kb = r & 1;
        int k = 2 * kp2 + kb;
        gW1i[i] = (k < 512) ? Whh0[c * 512 + k] : Wih0[c * 256 + (k - 512)];
    }
    if (i < 256 * 1024) {
        int kp2 = i >> 10, r = i & 1023, c = r >> 1, kb = r & 1;
        int k = 2 * kp2 + kb;
        gW2i[i] = Wih1[c * 512 + k] + Whh1[c * 512 + k];
    }
    if (i < 256 * 512) {
        int kp2 = i >> 9, r = i & 511, o = r >> 1, kb = r & 1;
        int k = 2 * kp2 + kb;
        gW3i[i] = Wout[o * 512 + k];
    }
}

// ---------- main persistent kernel ----------
__global__ void __launch_bounds__(512, 1) __cluster_dims__(8, 1, 1)
rnn_main(const float* __restrict__ x, const float* __restrict__ h0,
         const float* __restrict__ bih0, const float* __restrict__ bhh0,
         const float* __restrict__ bih1, const float* __restrict__ bhh1,
         const float* __restrict__ bout, float* __restrict__ out) {
    extern __shared__ float smem[];
    float* W2S  = smem;
    u64*   AST  = reinterpret_cast<u64*>(smem + AST_OFF);   // [m][384]
    float* SCRA = smem + SCR_OFF;                           // 12 x 512
    float* SCRB = smem + SCR_OFF;                           // 16 x 512 (overlay)
    float* SCRC = smem + SCR_OFF + SCRC_REL;                // 4 x 256
    float* b0s = smem + B0_OFF;
    float* bcs = smem + BC_OFF;
    float* bos = smem + BO_OFF;

    const int tid  = threadIdx.x;
    const int lane = tid & 31;
    const int ws   = tid >> 5;
    const int grp8 = (blockIdx.x >> 3) * 8;
    const int rank = blockIdx.x & 7;
    const int nb = rank * 64;
    const int ob = rank * 32;

    uint32_t smem_u32;
    asm("{ .reg .u64 t; cvta.to.shared.u64 t, %1; cvt.u32.u64 %0, t; }"
        : "=r"(smem_u32) : "l"(smem));
    const uint32_t mbBlo = smem_u32 + MBB_LO * 4;
    const uint32_t mbBhi = smem_u32 + MBB_HI * 4;
    const uint32_t mbAlo = smem_u32 + MBA_LO * 4;
    const uint32_t mbAhi = smem_u32 + MBA_HI * 4;

    // ---- biases ----
    if (tid < 64)       b0s[tid] = bih0[nb + tid] + bhh0[nb + tid];
    else if (tid < 128) { int c = tid - 64; bcs[c] = bih1[nb + c] + bhh1[nb + c]; }
    else if (tid < 160) { int c = tid - 128; bos[c] = bout[ob + c]; }

    // ---- W2 slice into SMEM ----
    for (int i = tid; i < 32768; i += 512) {
        int kp2 = i >> 7, rem = i & 127;
        W2S[i] = gW2i[kp2 * 1024 + rank * 128 + rem];
    }

    // ---- initial staging: h0 + x0 ----
    const int sm_ = tid >> 6, q = tid & 63;
    {
        float4* f4A = reinterpret_cast<float4*>(AST);   // 192 float4 per m
        const float4* hsrc = reinterpret_cast<const float4*>(h0 + (size_t)(grp8 + sm_) * H_);
        f4A[sm_ * 192 + q]      = __ldg(hsrc + q);
        f4A[sm_ * 192 + 64 + q] = __ldg(hsrc + q + 64);
        const float4* xsrc = reinterpret_cast<const float4*>(x + (size_t)(grp8 + sm_) * T_ * I_);
        f4A[sm_ * 192 + 128 + q] = __ldg(xsrc + q);
    }

    if (tid == 0) {
        mbar_init(mbBlo, 1); mbar_init(mbBhi, 1);
        mbar_init(mbAlo, 1); mbar_init(mbAhi, 1);
        mbar_arm(mbBlo, TX_HALF); mbar_arm(mbBhi, TX_HALF);   // for step 0's h1
    }
    __syncthreads();
    cluster_bar();   // once: mbars + SMEM visible cluster-wide

    // ---- base pointers ----
    const int cw = ws - 12;
    const u64x2* wA = reinterpret_cast<const u64x2*>(gW1i) + (size_t)(ws * 32) * 256 + rank * 32 + lane;
    const u64x2* aA = reinterpret_cast<const u64x2*>(AST) + ws * 16;                 // + m*192 + blk
    const u64*   wC = reinterpret_cast<const u64*>(gW3i) + (size_t)((cw < 0 ? 0 : cw) * 64) * 256 + ob + lane;
    const u64x2* aC = reinterpret_cast<const u64x2*>(AST) + (cw < 0 ? 0 : cw) * 32;  // + m*192 + blk
    const u64x2* wB = reinterpret_cast<const u64x2*>(W2S) + ws * 16 * 32 + lane;     // rows of 32
    const u64x2* aB = reinterpret_cast<const u64x2*>(smem + ASB_OFF) + ws * 8;       // + m*128 + blk

    const int rm = tid >> 5, rc = tid & 31;                    // reducers (tid<256)
    const uint32_t dstB = smem_u32 + (uint32_t)(ASB_OFF * 4) + (uint32_t)((rm * 256 + (nb >> 1) + rc) * 8);
    const uint32_t dstA = smem_u32 + (uint32_t)(AST_OFF * 4) + (uint32_t)((rm * 384 + (nb >> 1) + rc) * 8);
    const uint32_t myMbB = (rank < 4) ? mbBlo : mbBhi;
    const uint32_t myMbA = (rank < 4) ? mbAlo : mbAhi;
    const int em = (tid - 256) >> 5, ec = tid & 31;            // epilogue (tid>=256)

    for (int t = 0; t <= T_; t++) {
        const int doA = (t < T_), doC = (t > 0);
        const uint32_t pPrev = (uint32_t)((t - 1) & 1);
        const uint32_t pCur  = (uint32_t)(t & 1);

        float4 xr;
        if (doA) {
            int tn = (t + 1 < T_) ? (t + 1) : (T_ - 1);
            xr = __ldg(reinterpret_cast<const float4*>(
                x + ((size_t)(grp8 + sm_) * T_ + tn) * I_) + q);
        }

        // ============ Phase A (warps 0-11) / C(t-1) (warps 12-15) ============
        u64 acc[8][2];   // A partials
        u64 accc[8];     // C partials
        if (doA && ws < 12) {
            if (t) {
                if (ws < 4)      mbar_wait(mbAlo, pPrev);
                else if (ws < 8) mbar_wait(mbAhi, pPrev);
                // ws 8-11: x region, no wait
            }
#pragma unroll
            for (int m = 0; m < 8; m++) { acc[m][0] = 0; acc[m][1] = 0; }
            u64x2 pw[2][2];
            pw[0][0] = wA[0];   pw[0][1] = wA[256];
            pw[1][0] = wA[512]; pw[1][1] = wA[768];
#pragma unroll 4
            for (int blk = 0; blk < 16; blk++) {
                const int s = blk & 1;
                u64x2 w0 = pw[s][0], w1 = pw[s][1];
                if (blk < 14) {
                    pw[s][0] = wA[(size_t)(2 * blk + 4) * 256];
                    pw[s][1] = wA[(size_t)(2 * blk + 5) * 256];
                }
#pragma unroll
                for (int m = 0; m < 8; m++) {
                    u64x2 a2 = aA[m * 192 + blk];
                    acc[m][0] = fma2_(a2.x, w0.x, acc[m][0]);
                    acc[m][1] = fma2_(a2.x, w0.y, acc[m][1]);
                    acc[m][0] = fma2_(a2.y, w1.x, acc[m][0]);
                    acc[m][1] = fma2_(a2.y, w1.y, acc[m][1]);
                }
            }
        } else if (ws >= 12 && doC) {
            mbar_wait(mbAlo, pPrev);
            mbar_wait(mbAhi, pPrev);
#pragma unroll
            for (int m = 0; m < 8; m++) accc[m] = 0;
            u64 pwc[2][2];
            pwc[0][0] = wC[0];   pwc[0][1] = wC[256];
            pwc[1][0] = wC[512]; pwc[1][1] = wC[768];
#pragma unroll 4
            for (int blk = 0; blk < 32; blk++) {
                const int s = blk & 1;
                u64 w0 = pwc[s][0], w1 = pwc[s][1];
                if (blk < 30) {
                    pwc[s][0] = wC[(size_t)(2 * blk + 4) * 256];
                    pwc[s][1] = wC[(size_t)(2 * blk + 5) * 256];
                }
#pragma unroll
                for (int m = 0; m < 8; m++) {
                    u64x2 a2 = aC[m * 192 + blk];
                    accc[m] = fma2_(a2.x, w0, accc[m]);
                    accc[m] = fma2_(a2.y, w1, accc[m]);
                }
            }
        }
        __syncthreads();  // (a): AST reads done; prev-step SCR readers done

        if (doA && ws < 12) {        // A-combine -> SCRA
#pragma unroll
            for (int m = 0; m < 8; m++) {
                float e0, o0, e1, o1;
                unpack2(acc[m][0], e0, o0); unpack2(acc[m][1], e1, o1);
                *reinterpret_cast<float2*>(&SCRA[ws * 512 + m * 64 + 2 * lane]) =
                    make_float2(e0 + o0, e1 + o1);
            }
        } else if (ws >= 12 && doC) { // C-combine -> SCRC
#pragma unroll
            for (int m = 0; m < 8; m++) {
                float e, o; unpack2(accc[m], e, o);
                SCRC[cw * 256 + m * 32 + lane] = e + o;
            }
        }
        if (doA) {
            reinterpret_cast<float4*>(AST)[sm_ * 192 + 128 + q] = xr;   // stage x_{t+1}
            if (tid == 0) { mbar_arm(mbAlo, TX_HALF); mbar_arm(mbAhi, TX_HALF); }
        }
        __syncthreads();  // (b)

        if (doC && tid >= 256) {      // y(t-1) epilogue on spare threads
            float s = SCRC[em * 32 + ec] + SCRC[256 + em * 32 + ec]
                    + SCRC[512 + em * 32 + ec] + SCRC[768 + em * 32 + ec] + bos[ec];
            out[(size_t)(grp8 + em) * (T_ * O_) + (size_t)(t - 1) * O_ + ob + ec] = s;
        }
        if (!doA) break;

        if (tid < 256) {              // h1-reduce (12-way) + tanh + publish halves
            const float* base = SCRA + rm * 64 + 2 * rc;
            u64 s = *reinterpret_cast<const u64*>(base);
#pragma unroll
            for (int w2 = 1; w2 < 12; w2++)
                s = add2_(s, *reinterpret_cast<const u64*>(base + w2 * 512));
            s = add2_(s, *reinterpret_cast<const u64*>(b0s + 2 * rc));
            float e, o; unpack2(s, e, o);
            u64 v = pack2(mytanh(e), mytanh(o));
#pragma unroll
            for (int r = 0; r < 8; r++)
                st_async64(mapa_u32(dstB, r), v, mapa_u32(myMbB, r));
        }

        // ============ Phase B: h2 = tanh(h1 @ Wc^T + bc) ============
        if (ws < 8) mbar_wait(mbBlo, pCur); else mbar_wait(mbBhi, pCur);
#pragma unroll
        for (int m = 0; m < 8; m++) { acc[m][0] = 0; acc[m][1] = 0; }
#pragma unroll
        for (int blk = 0; blk < 8; blk++) {
            u64x2 w0 = wB[(2 * blk) * 32];
            u64x2 w1 = wB[(2 * blk + 1) * 32];
#pragma unroll
            for (int m = 0; m < 8; m++) {
                u64x2 a2 = aB[m * 128 + blk];
                acc[m][0] = fma2_(a2.x, w0.x, acc[m][0]);
                acc[m][1] = fma2_(a2.x, w0.y, acc[m][1]);
                acc[m][0] = fma2_(a2.y, w1.x, acc[m][0]);
                acc[m][1] = fma2_(a2.y, w1.y, acc[m][1]);
            }
        }
        __syncthreads();  // (c): SCRA/SCRC readers done; safe to overlay SCRB
#pragma unroll
        for (int m = 0; m < 8; m++) {
            float e0, o0, e1, o1;
            unpack2(acc[m][0], e0, o0); unpack2(acc[m][1], e1, o1);
            *reinterpret_cast<float2*>(&SCRB[ws * 512 + m * 64 + 2 * lane]) =
                make_float2(e0 + o0, e1 + o1);
        }
        if (tid == 0) { mbar_arm(mbBlo, TX_HALF); mbar_arm(mbBhi, TX_HALF); }  // for t+1
        __syncthreads();  // (d)

        if (tid < 256) {              // h2-reduce (16-way) + tanh + publish halves
            const float* base = SCRB + rm * 64 + 2 * rc;
            u64 s = *reinterpret_cast<const u64*>(base);
#pragma unroll
            for (int w2 = 1; w2 < 16; w2++)
                s = add2_(s, *reinterpret_cast<const u64*>(base + w2 * 512));
            s = add2_(s, *reinterpret_cast<const u64*>(bcs + 2 * rc));
            float e, o; unpack2(s, e, o);
            u64 v = pack2(mytanh(e), mytanh(o));
#pragma unroll
            for (int r = 0; r < 8; r++)
                st_async64(mapa_u32(dstA, r), v, mapa_u32(myMbA, r));
        }
    }
    cluster_bar();  // keep SMEM alive until all cluster traffic retired
}

extern "C" void kernel_launch(void* const* d_in, const int* in_sizes, int n_in,
                              void* d_out, int out_size) {
    const float* x    = (const float*)d_in[0];
    const float* h0   = (const float*)d_in[1];
    const float* Wih0 = (const float*)d_in[2];
    const float* bih0 = (const float*)d_in[3];
    const float* Whh0 = (const float*)d_in[4];
    const float* bhh0 = (const float*)d_in[5];
    const float* Wih1 = (const float*)d_in[6];
    const float* bih1 = (const float*)d_in[7];
    const float* Whh1 = (const float*)d_in[8];
    const float* bhh1 = (const float*)d_in[9];
    const float* Wout = (const float*)d_in[10];
    const float* bout = (const float*)d_in[11];
    float* out = (float*)d_out;

    cudaFuncSetAttribute(rnn_main, cudaFuncAttributeMaxDynamicSharedMemorySize, SMEM_BYTES);

    rnn_prep<<<1536, 256>>>(Wih0, Whh0, Wih1, Whh1, Wout);
    rnn_main<<<128, 512, SMEM_BYTES>>>(x, h0, bih0, bhh0, bih1, bhh1, bout, out);
}